// round 2
// baseline (speedup 1.0000x reference)
#include <cuda_runtime.h>

#define NN 100000
#define EE 800000
#define D  128
#define TM 64
#define WP 132   // padded pitch (floats) for transposed weight tiles: conflict-free LDS.128
#define EPSF 1e-5f

// Scratch (allocation-free rule: __device__ globals)
__device__ __align__(16) float g_agg[(size_t)NN * D];   // segment sums
__device__ float g_deg[NN];                             // degrees

// ---------------------------------------------------------------------------
// Kernel 0: zero the accumulators (must be re-zeroed every replay)
// ---------------------------------------------------------------------------
__global__ void zero_kernel() {
    int idx = blockIdx.x * blockDim.x + threadIdx.x;
    int stride = gridDim.x * blockDim.x;
    float4 z = make_float4(0.f, 0.f, 0.f, 0.f);
    float4* a4 = reinterpret_cast<float4*>(g_agg);
    const int n4 = NN * (D / 4);
    for (int i = idx; i < n4; i += stride) a4[i] = z;
    for (int i = idx; i < NN; i += stride) g_deg[i] = 0.f;
}

// ---------------------------------------------------------------------------
// Kernel 1: edge scatter. One warp per edge: 32 lanes x float4 = 128 floats.
// Vectorized red.global.add.v4.f32 (sm_90+) quarters the atomic op count.
// NOTE: edge_index is int32 on device (JAX x64 disabled -> int64 request
// silently lowers to int32).
// ---------------------------------------------------------------------------
__global__ __launch_bounds__(256) void scatter_kernel(
    const float* __restrict__ x, const int* __restrict__ ei)
{
    int gw   = (blockIdx.x * 256 + threadIdx.x) >> 5;
    int lane = threadIdx.x & 31;
    if (gw >= EE) return;
    int s = ei[gw];
    int d = ei[EE + gw];

    float4 v = ((const float4*)x)[(size_t)s * (D / 4) + lane];
    float* dst = g_agg + (size_t)d * D + lane * 4;
    asm volatile("red.global.add.v4.f32 [%0], {%1, %2, %3, %4};"
                 :: "l"(dst), "f"(v.x), "f"(v.y), "f"(v.z), "f"(v.w)
                 : "memory");
    if (lane == 0) atomicAdd(&g_deg[d], 1.0f);
}

// ---------------------------------------------------------------------------
// Kernel 2: fused dual-GEMM + bias + ReLU + LayerNorm.
// Block = 256 threads, tile = 64 nodes x 128 out cols.
// Weights stored TRANSPOSED in smem as W_t[k][o] with pitch WP=132 so that
// the inner-loop W loads (16 lanes x contiguous 32B) are bank-conflict-free.
// Thread (ty,tx): 4 node rows x 8 out cols register tile -> 64 FMA / k-step.
// LayerNorm reduction: 16 threads per node row are contiguous lanes ->
// __shfl_xor within 16-lane groups.
// ---------------------------------------------------------------------------
extern __shared__ float smem_f[];

__global__ __launch_bounds__(256, 1) void fused_kernel(
    const float* __restrict__ x,  const float* __restrict__ Ws,
    const float* __restrict__ Wn, const float* __restrict__ bias,
    const float* __restrict__ gamma, const float* __restrict__ beta,
    float* __restrict__ out)
{
    float* wst  = smem_f;                 // [D][WP]
    float* wnt  = wst + D * WP;           // [D][WP]
    float* xs   = wnt + D * WP;           // [TM][D]
    float* ms   = xs + TM * D;            // [TM][D]
    float* rdeg = ms + TM * D;            // [TM]

    const int tid  = threadIdx.x;
    const int base = blockIdx.x * TM;

    // Load weights transposed (gmem reads coalesced; strided smem stores are one-time)
    for (int idx = tid; idx < D * D; idx += 256) {
        int o = idx >> 7, k = idx & (D - 1);
        wst[k * WP + o] = Ws[idx];
        wnt[k * WP + o] = Wn[idx];
    }
    // Reciprocal clamped degrees
    if (tid < TM) {
        int n = base + tid;
        float dg = (n < NN) ? g_deg[n] : 1.f;
        rdeg[tid] = 1.f / fmaxf(dg, 1.f);
    }
    __syncthreads();

    // Load x tile and neigh-mean tile (agg * rdeg), float4-vectorized
    for (int idx = tid; idx < TM * (D / 4); idx += 256) {
        int nl = idx >> 5, k4 = idx & 31;
        int n = base + nl;
        float4 xv = make_float4(0.f, 0.f, 0.f, 0.f);
        float4 av = xv;
        if (n < NN) {
            xv = ((const float4*)x)[(size_t)n * 32 + k4];
            av = ((const float4*)g_agg)[(size_t)n * 32 + k4];
        }
        float r = rdeg[nl];
        av.x *= r; av.y *= r; av.z *= r; av.w *= r;
        ((float4*)xs)[nl * 32 + k4] = xv;
        ((float4*)ms)[nl * 32 + k4] = av;
    }
    __syncthreads();

    const int tx = tid & 15;   // col group: cols tx*8 .. tx*8+7
    const int ty = tid >> 4;   // node group: nodes ty*4 .. ty*4+3

    float acc[4][8];
    #pragma unroll
    for (int i = 0; i < 4; i++)
        #pragma unroll
        for (int j = 0; j < 8; j++) acc[i][j] = 0.f;

    const float* xr  = xs + (ty * 4) * D;
    const float* mr  = ms + (ty * 4) * D;
    const float* wso = wst + tx * 8;
    const float* wno = wnt + tx * 8;

    #pragma unroll 4
    for (int k = 0; k < D; k++) {
        float a[4], m[4];
        #pragma unroll
        for (int i = 0; i < 4; i++) { a[i] = xr[i * D + k]; m[i] = mr[i * D + k]; }
        float4 w0 = *(const float4*)(wso + k * WP);
        float4 w1 = *(const float4*)(wso + k * WP + 4);
        float4 v0 = *(const float4*)(wno + k * WP);
        float4 v1 = *(const float4*)(wno + k * WP + 4);
        float w[8] = {w0.x, w0.y, w0.z, w0.w, w1.x, w1.y, w1.z, w1.w};
        float v[8] = {v0.x, v0.y, v0.z, v0.w, v1.x, v1.y, v1.z, v1.w};
        #pragma unroll
        for (int i = 0; i < 4; i++)
            #pragma unroll
            for (int j = 0; j < 8; j++)
                acc[i][j] = fmaf(a[i], w[j], fmaf(m[i], v[j], acc[i][j]));
    }

    // Epilogue: bias + ReLU + LayerNorm (biased var, matching jnp.var)
    float bi[8], ga[8], be[8];
    #pragma unroll
    for (int j = 0; j < 8; j++) {
        int o = tx * 8 + j;
        bi[j] = bias[o]; ga[j] = gamma[o]; be[j] = beta[o];
    }

    #pragma unroll
    for (int i = 0; i < 4; i++) {
        float s = 0.f, s2 = 0.f;
        #pragma unroll
        for (int j = 0; j < 8; j++) {
            float t = fmaxf(acc[i][j] + bi[j], 0.f);
            acc[i][j] = t;
            s  += t;
            s2 += t * t;
        }
        // reduce across the 16 lanes sharing this node row (laneMask < 16)
        #pragma unroll
        for (int off = 8; off >= 1; off >>= 1) {
            s  += __shfl_xor_sync(0xffffffffu, s,  off);
            s2 += __shfl_xor_sync(0xffffffffu, s2, off);
        }
        float mean = s * (1.f / D);
        float var  = s2 * (1.f / D) - mean * mean;
        float rstd = rsqrtf(var + EPSF);
        int n = base + ty * 4 + i;
        if (n < NN) {
            #pragma unroll
            for (int j = 0; j < 8; j++) {
                int o = tx * 8 + j;
                out[(size_t)n * D + o] = (acc[i][j] - mean) * rstd * ga[j] + be[j];
            }
        }
    }
}

// ---------------------------------------------------------------------------
extern "C" void kernel_launch(void* const* d_in, const int* in_sizes, int n_in,
                              void* d_out, int out_size) {
    const float* x     = (const float*)d_in[0];
    const int*   ei    = (const int*)d_in[1];
    const float* Ws    = (const float*)d_in[2];
    const float* Wn    = (const float*)d_in[3];
    const float* bias  = (const float*)d_in[4];
    const float* gamma = (const float*)d_in[5];
    const float* beta  = (const float*)d_in[6];
    float*       out   = (float*)d_out;

    size_t smem = (size_t)(2 * D * WP + 2 * TM * D + TM) * sizeof(float); // 200,960 B
    cudaFuncSetAttribute(fused_kernel,
                         cudaFuncAttributeMaxDynamicSharedMemorySize, (int)smem);

    zero_kernel<<<1024, 256>>>();

    int scatter_blocks = (EE * 32 + 255) / 256;  // one warp per edge
    scatter_kernel<<<scatter_blocks, 256>>>(x, ei);

    int grid = (NN + TM - 1) / TM;
    fused_kernel<<<grid, 256, smem>>>(x, Ws, Wn, bias, gamma, beta, out);
}

// round 3
// speedup vs baseline: 1.7418x; 1.7418x over previous
#include <cuda_runtime.h>
#include <cstdint>

#define NN 100000
#define EE 800000
#define D  128
#define MB 128      // nodes per block (fused kernel)
#define AP 132      // A smem pitch (floats): conflict-free frag loads
#define WPI 136     // W smem pitch (floats): conflict-free frag loads
#define EPSF 1e-5f

// Scratch (allocation-free rule: __device__ globals)
__device__ __align__(16) float g_agg[(size_t)NN * D];
__device__ float g_deg[NN];

// ---------------------------------------------------------------------------
// Kernel 0: zero accumulators (re-zeroed every replay)
// ---------------------------------------------------------------------------
__global__ void zero_kernel() {
    int idx = blockIdx.x * blockDim.x + threadIdx.x;
    int stride = gridDim.x * blockDim.x;
    float4 z = make_float4(0.f, 0.f, 0.f, 0.f);
    float4* a4 = reinterpret_cast<float4*>(g_agg);
    const int n4 = NN * (D / 4);
    for (int i = idx; i < n4; i += stride) a4[i] = z;
    for (int i = idx; i < NN; i += stride) g_deg[i] = 0.f;
}

// ---------------------------------------------------------------------------
// Kernel 1: edge scatter (one warp per edge, red.global.add.v4.f32)
// edge_index is int32 on device (JAX x64 disabled).
// ---------------------------------------------------------------------------
__global__ __launch_bounds__(256) void scatter_kernel(
    const float* __restrict__ x, const int* __restrict__ ei)
{
    int gw   = (blockIdx.x * 256 + threadIdx.x) >> 5;
    int lane = threadIdx.x & 31;
    if (gw >= EE) return;
    int s = ei[gw];
    int d = ei[EE + gw];

    float4 v = ((const float4*)x)[(size_t)s * (D / 4) + lane];
    float* dst = g_agg + (size_t)d * D + lane * 4;
    asm volatile("red.global.add.v4.f32 [%0], {%1, %2, %3, %4};"
                 :: "l"(dst), "f"(v.x), "f"(v.y), "f"(v.z), "f"(v.w)
                 : "memory");
    if (lane == 0) atomicAdd(&g_deg[d], 1.0f);
}

// ---------------------------------------------------------------------------
// Kernel 2: fused dual-GEMM (tf32 mma.sync) + bias + ReLU + LayerNorm.
// out = [x | neigh_mean] @ [Ws | Wn]^T  -> K=256 as two K=128 phases.
// Block 256 thr = 8 warps: warp_m in 0..3 (32 rows each), warp_n in 0..1
// (64 cols each). Warp tile: 2 M-tiles x 8 N-tiles of m16n8k8.
// ---------------------------------------------------------------------------
__device__ __forceinline__ uint32_t f2tf32(float f) {
    uint32_t r;
    asm("cvt.rna.tf32.f32 %0, %1;" : "=r"(r) : "f"(f));
    return r;
}

extern __shared__ float smem_f[];

__global__ __launch_bounds__(256, 1) void fused_kernel(
    const float* __restrict__ x,  const float* __restrict__ Ws,
    const float* __restrict__ Wn, const float* __restrict__ bias,
    const float* __restrict__ gamma, const float* __restrict__ beta,
    float* __restrict__ out)
{
    float* As     = smem_f;                 // [MB][AP]
    float* Bsm    = As + MB * AP;           // [D][WPI], k-major weights
    float* red_s  = Bsm + D * WPI;          // [MB][2]
    float* red_s2 = red_s + MB * 2;         // [MB][2]
    float* rdeg   = red_s2 + MB * 2;        // [MB]
    float* cbuf   = rdeg + MB;              // bias | gamma | beta  [3*D]

    const int tid  = threadIdx.x;
    const int base = blockIdx.x * MB;
    const int lane = tid & 31;
    const int wid  = tid >> 5;
    const int wm   = wid & 3;               // row group: wm*32
    const int wn   = wid >> 2;              // col group: wn*64
    const int g    = lane >> 2;             // 0..7
    const int tg   = lane & 3;              // 0..3

    // Stage constants + reciprocal degrees (before first sync)
    if (tid < D) {
        cbuf[tid]         = bias[tid];
        cbuf[D + tid]     = gamma[tid];
        cbuf[2 * D + tid] = beta[tid];
    } else if (tid < D + MB) {
        int n = base + (tid - D);
        float dg = (n < NN) ? g_deg[n] : 1.f;
        rdeg[tid - D] = 1.f / fmaxf(dg, 1.f);
    }

    float acc[2][8][4];
    #pragma unroll
    for (int t = 0; t < 2; t++)
        #pragma unroll
        for (int j = 0; j < 8; j++)
            #pragma unroll
            for (int e = 0; e < 4; e++) acc[t][j][e] = 0.f;

    #pragma unroll 1
    for (int phase = 0; phase < 2; phase++) {
        __syncthreads();   // smem reuse fence (covers rdeg/cbuf on phase 0)

        // Stage weights transposed: Bsm[k][o] = tf32(W[o][k])
        const float* W = phase ? Wn : Ws;
        for (int idx = tid; idx < D * D; idx += 256) {
            int o = idx >> 7, k = idx & (D - 1);
            Bsm[k * WPI + o] = __uint_as_float(f2tf32(W[idx]));
        }

        // Stage A tile (tf32): phase 0 = x rows; phase 1 = agg * rdeg
        for (int idx = tid; idx < MB * (D / 4); idx += 256) {
            int nl = idx >> 5, k4 = idx & 31;
            int n = base + nl;
            float4 v = make_float4(0.f, 0.f, 0.f, 0.f);
            if (n < NN) {
                if (phase == 0) {
                    v = ((const float4*)x)[(size_t)n * 32 + k4];
                } else {
                    v = ((const float4*)g_agg)[(size_t)n * 32 + k4];
                    float r = rdeg[nl];
                    v.x *= r; v.y *= r; v.z *= r; v.w *= r;
                }
            }
            float4 c;
            c.x = __uint_as_float(f2tf32(v.x));
            c.y = __uint_as_float(f2tf32(v.y));
            c.z = __uint_as_float(f2tf32(v.z));
            c.w = __uint_as_float(f2tf32(v.w));
            *(float4*)(As + nl * AP + k4 * 4) = c;
        }
        __syncthreads();

        // Main MMA loop: 16 k-steps of 8
        #pragma unroll
        for (int ks = 0; ks < 16; ks++) {
            const int kc = ks * 8;
            uint32_t b[8][2];
            #pragma unroll
            for (int j = 0; j < 8; j++) {
                b[j][0] = __float_as_uint(Bsm[(kc + tg)     * WPI + wn * 64 + j * 8 + g]);
                b[j][1] = __float_as_uint(Bsm[(kc + tg + 4) * WPI + wn * 64 + j * 8 + g]);
            }
            #pragma unroll
            for (int t = 0; t < 2; t++) {
                const int r0 = wm * 32 + t * 16 + g;
                uint32_t a0 = __float_as_uint(As[r0       * AP + kc + tg]);
                uint32_t a1 = __float_as_uint(As[(r0 + 8) * AP + kc + tg]);
                uint32_t a2 = __float_as_uint(As[r0       * AP + kc + tg + 4]);
                uint32_t a3 = __float_as_uint(As[(r0 + 8) * AP + kc + tg + 4]);
                #pragma unroll
                for (int j = 0; j < 8; j++) {
                    asm volatile(
                        "mma.sync.aligned.m16n8k8.row.col.f32.tf32.tf32.f32 "
                        "{%0,%1,%2,%3}, {%4,%5,%6,%7}, {%8,%9}, {%0,%1,%2,%3};"
                        : "+f"(acc[t][j][0]), "+f"(acc[t][j][1]),
                          "+f"(acc[t][j][2]), "+f"(acc[t][j][3])
                        : "r"(a0), "r"(a1), "r"(a2), "r"(a3),
                          "r"(b[j][0]), "r"(b[j][1]));
                }
            }
        }
    }

    // ---- Epilogue: bias + ReLU + LayerNorm ----
    // Thread holds rows: wm*32 + t*16 + h*8 + g  (t,h in {0,1})
    // cols: wn*64 + j*8 + tg*2 + e  (j in 0..7, e in {0,1}); value acc[t][j][2h+e]
    #pragma unroll
    for (int t = 0; t < 2; t++) {
        #pragma unroll
        for (int h = 0; h < 2; h++) {
            float s = 0.f, s2 = 0.f;
            #pragma unroll
            for (int j = 0; j < 8; j++) {
                #pragma unroll
                for (int e = 0; e < 2; e++) {
                    int col = wn * 64 + j * 8 + tg * 2 + e;
                    float v = fmaxf(acc[t][j][2 * h + e] + cbuf[col], 0.f);
                    acc[t][j][2 * h + e] = v;
                    s += v; s2 += v * v;
                }
            }
            s  += __shfl_xor_sync(0xffffffffu, s, 1);
            s  += __shfl_xor_sync(0xffffffffu, s, 2);
            s2 += __shfl_xor_sync(0xffffffffu, s2, 1);
            s2 += __shfl_xor_sync(0xffffffffu, s2, 2);
            if (tg == 0) {
                int row = wm * 32 + t * 16 + h * 8 + g;
                red_s [row * 2 + wn] = s;
                red_s2[row * 2 + wn] = s2;
            }
        }
    }
    __syncthreads();

    #pragma unroll
    for (int t = 0; t < 2; t++) {
        #pragma unroll
        for (int h = 0; h < 2; h++) {
            int row = wm * 32 + t * 16 + h * 8 + g;
            float s  = red_s [row * 2] + red_s [row * 2 + 1];
            float s2 = red_s2[row * 2] + red_s2[row * 2 + 1];
            float mean = s * (1.f / D);
            float var  = s2 * (1.f / D) - mean * mean;
            float rstd = rsqrtf(var + EPSF);
            int n = base + row;
            if (n < NN) {
                #pragma unroll
                for (int j = 0; j < 8; j++) {
                    int col = wn * 64 + j * 8 + tg * 2;
                    float2 o2;
                    o2.x = (acc[t][j][2 * h + 0] - mean) * rstd * cbuf[D + col]     + cbuf[2 * D + col];
                    o2.y = (acc[t][j][2 * h + 1] - mean) * rstd * cbuf[D + col + 1] + cbuf[2 * D + col + 1];
                    *(float2*)(out + (size_t)n * D + col) = o2;
                }
            }
        }
    }
}

// ---------------------------------------------------------------------------
extern "C" void kernel_launch(void* const* d_in, const int* in_sizes, int n_in,
                              void* d_out, int out_size) {
    const float* x     = (const float*)d_in[0];
    const int*   ei    = (const int*)d_in[1];
    const float* Ws    = (const float*)d_in[2];
    const float* Wn    = (const float*)d_in[3];
    const float* bias  = (const float*)d_in[4];
    const float* gamma = (const float*)d_in[5];
    const float* beta  = (const float*)d_in[6];
    float*       out   = (float*)d_out;

    size_t smem = (size_t)(MB * AP + D * WPI + MB * 2 * 2 + MB + 3 * D) * sizeof(float);
    cudaFuncSetAttribute(fused_kernel,
                         cudaFuncAttributeMaxDynamicSharedMemorySize, (int)smem);

    zero_kernel<<<1024, 256>>>();

    int scatter_blocks = (EE * 32 + 255) / 256;  // one warp per edge
    scatter_kernel<<<scatter_blocks, 256>>>(x, ei);

    int grid = (NN + MB - 1) / MB;
    fused_kernel<<<grid, 256, smem>>>(x, Ws, Wn, bias, gamma, beta, out);
}